// round 16
// baseline (speedup 1.0000x reference)
#include <cuda_runtime.h>
#include <cuda_bf16.h>
#include <cuda_fp16.h>
#include <stdint.h>
#include <math.h>

#define TPB 512

namespace {

constexpr int N = 64;
constexpr int F = 128;
constexpr int APAD = 68;   // [n][kpair] packed stride (A ops, q, k)
constexpr int TPAD = 36;   // [dh][mpair] & [hh][n][mpair] stride
constexpr float NEGV = -1e9f;
constexpr float INV_SQRT_DH = 0.125f;

// Fragment-ordered split weights: [15 mats][kstep 8][ntile 16][lane 32] x uint4
__device__ uint4 g_wfrag[15 * 8 * 16 * 32];

struct __align__(16) Smem {
  float h[N][F];                         // residual (1W + 1R per layer)
  uint32_t ahp[N][APAD], alp[N][APAD];   // LN(h)/msg split-bf16; q fp16 (ahp only)
  uint32_t u1h[4608];                    // k fp16 [m][APAD]  then attn fp16 [hh*64+n][TPAD]
  uint32_t vth[F][TPAD];                 // v fp16 transposed [dh][mpair]
  float bias12[2][2][64][64];            // cached edge bias for layers 1,2
  float rmx[2][64][2], rsm[2][64][2];
  float pS[64][8], pQ[64][8];            // LN row-stat partials (8 col groups)
  float coords[N][3];
  float mrow[N];
  float bf_all[3][F];
  float Wel[3][7][2];
};

__device__ __forceinline__ void mma_bf16(float* d,
    uint32_t a0, uint32_t a1, uint32_t a2, uint32_t a3,
    uint32_t b0, uint32_t b1)
{
  asm volatile(
    "mma.sync.aligned.m16n8k16.row.col.f32.bf16.bf16.f32 "
    "{%0,%1,%2,%3}, {%4,%5,%6,%7}, {%8,%9}, {%0,%1,%2,%3};\n"
    : "+f"(d[0]), "+f"(d[1]), "+f"(d[2]), "+f"(d[3])
    : "r"(a0), "r"(a1), "r"(a2), "r"(a3), "r"(b0), "r"(b1));
}

__device__ __forceinline__ void mma_f16(float* d,
    uint32_t a0, uint32_t a1, uint32_t a2, uint32_t a3,
    uint32_t b0, uint32_t b1)
{
  asm volatile(
    "mma.sync.aligned.m16n8k16.row.col.f32.f16.f16.f32 "
    "{%0,%1,%2,%3}, {%4,%5,%6,%7}, {%8,%9}, {%0,%1,%2,%3};\n"
    : "+f"(d[0]), "+f"(d[1]), "+f"(d[2]), "+f"(d[3])
    : "r"(a0), "r"(a1), "r"(a2), "r"(a3), "r"(b0), "r"(b1));
}

__device__ __forceinline__ void mma3(float* d,
    uint32_t ah0, uint32_t ah1, uint32_t ah2, uint32_t ah3,
    uint32_t al0, uint32_t al1, uint32_t al2, uint32_t al3,
    uint4 w)
{
  mma_bf16(d, ah0, ah1, ah2, ah3, w.x, w.y);
  mma_bf16(d, ah0, ah1, ah2, ah3, w.z, w.w);
  mma_bf16(d, al0, al1, al2, al3, w.x, w.y);
}

__device__ __forceinline__ void ldsm4(uint32_t& r0, uint32_t& r1,
                                      uint32_t& r2, uint32_t& r3, uint32_t a)
{
  asm volatile("ldmatrix.sync.aligned.m8n8.x4.shared.b16 {%0,%1,%2,%3}, [%4];"
               : "=r"(r0), "=r"(r1), "=r"(r2), "=r"(r3) : "r"(a));
}

__device__ __forceinline__ void pack2(float x, float y,
                                      uint32_t* hp, uint32_t* lp)
{
  __nv_bfloat162 h2 = __floats2bfloat162_rn(x, y);
  float hx = __bfloat162float(h2.x), hy = __bfloat162float(h2.y);
  __nv_bfloat162 l2 = __floats2bfloat162_rn(x - hx, y - hy);
  *hp = *reinterpret_cast<uint32_t*>(&h2);
  *lp = *reinterpret_cast<uint32_t*>(&l2);
}

__device__ __forceinline__ uint32_t packh2(float x, float y)
{
  __half2 h = __floats2half2_rn(x, y);
  return *reinterpret_cast<uint32_t*>(&h);
}

__device__ __forceinline__ uint32_t s2u(const void* p) {
  return (uint32_t)__cvta_generic_to_shared(p);
}

// Write LN row partial sums/sumsq from the register h tile (M32xN16 mapping).
__device__ __forceinline__ void ln_partials(const float hv[4][4], int r0q,
    int cg, int tig, float (*pS)[8], float (*pQ)[8])
{
  float s0 = (hv[0][0] + hv[0][1]) + (hv[1][0] + hv[1][1]);
  float s1 = (hv[0][2] + hv[0][3]) + (hv[1][2] + hv[1][3]);
  float s2 = (hv[2][0] + hv[2][1]) + (hv[3][0] + hv[3][1]);
  float s3 = (hv[2][2] + hv[2][3]) + (hv[3][2] + hv[3][3]);
  float q0 = (hv[0][0]*hv[0][0] + hv[0][1]*hv[0][1]) + (hv[1][0]*hv[1][0] + hv[1][1]*hv[1][1]);
  float q1 = (hv[0][2]*hv[0][2] + hv[0][3]*hv[0][3]) + (hv[1][2]*hv[1][2] + hv[1][3]*hv[1][3]);
  float q2 = (hv[2][0]*hv[2][0] + hv[2][1]*hv[2][1]) + (hv[3][0]*hv[3][0] + hv[3][1]*hv[3][1]);
  float q3 = (hv[2][2]*hv[2][2] + hv[2][3]*hv[2][3]) + (hv[3][2]*hv[3][2] + hv[3][3]*hv[3][3]);
#pragma unroll
  for (int o = 1; o <= 2; o <<= 1) {
    s0 += __shfl_xor_sync(0xffffffffu, s0, o);
    s1 += __shfl_xor_sync(0xffffffffu, s1, o);
    s2 += __shfl_xor_sync(0xffffffffu, s2, o);
    s3 += __shfl_xor_sync(0xffffffffu, s3, o);
    q0 += __shfl_xor_sync(0xffffffffu, q0, o);
    q1 += __shfl_xor_sync(0xffffffffu, q1, o);
    q2 += __shfl_xor_sync(0xffffffffu, q2, o);
    q3 += __shfl_xor_sync(0xffffffffu, q3, o);
  }
  if (tig == 0) {
    pS[r0q     ][cg] = s0;  pQ[r0q     ][cg] = q0;
    pS[r0q +  8][cg] = s1;  pQ[r0q +  8][cg] = q1;
    pS[r0q + 16][cg] = s2;  pQ[r0q + 16][cg] = q2;
    pS[r0q + 24][cg] = s3;  pQ[r0q + 24][cg] = q3;
  }
}

// Read stats, normalize register h tile, pack into ahp/alp.
__device__ __forceinline__ void ln_pack(const float hv[4][4], int r0q, int kp0,
    const float (*pS)[8], const float (*pQ)[8],
    uint32_t (*ahp)[APAD], uint32_t (*alp)[APAD])
{
#pragma unroll
  for (int rr = 0; rr < 4; ++rr) {
    const int r = r0q + rr * 8;
    float4 sa = *(const float4*)&pS[r][0];
    float4 sb = *(const float4*)&pS[r][4];
    float sum = ((sa.x + sa.y) + (sa.z + sa.w)) + ((sb.x + sb.y) + (sb.z + sb.w));
    float4 qa = *(const float4*)&pQ[r][0];
    float4 qb = *(const float4*)&pQ[r][4];
    float qs = ((qa.x + qa.y) + (qa.z + qa.w)) + ((qb.x + qb.y) + (qb.z + qb.w));
    float mean = sum * (1.f / 128.f);
    float var = qs * (1.f / 128.f) - mean * mean;
    float inv = rsqrtf(var + 1e-5f);
    const int ub = (rr >> 1) * 2;
    const int ib = (rr & 1) * 2;
    float n0 = (hv[ub][ib]     - mean) * inv;
    float n1 = (hv[ub][ib + 1] - mean) * inv;
    float n2 = (hv[ub + 1][ib]     - mean) * inv;
    float n3 = (hv[ub + 1][ib + 1] - mean) * inv;
    pack2(n0, n1, &ahp[r][kp0],     &alp[r][kp0]);
    pack2(n2, n3, &ahp[r][kp0 + 4], &alp[r][kp0 + 4]);
  }
}

__global__ void __launch_bounds__(TPB, 1) gnn_kernel(
    const float* __restrict__ g_coords,
    const int*   __restrict__ g_species,
    const int*   __restrict__ g_mask,
    const float* __restrict__ g_embed,
    const float* __restrict__ g_We,
    const float* __restrict__ g_bf,
    float* __restrict__ g_out)
{
  extern __shared__ unsigned char smem_raw[];
  Smem& s = *reinterpret_cast<Smem*>(smem_raw);
  const int b = blockIdx.x;
  const int tid = threadIdx.x;

  const int warp = tid >> 5, lane = tid & 31;
  // attention mapping (M=16 x N=32 tiles)
  const int mb = (warp & 3) << 4;
  const int lm = lane >> 2, tig = lane & 3;
  const int rA = mb + lm, rB = mb + lm + 8;
  const int hh   = warp >> 3;
  const int mblk = (warp >> 2) & 1;
  // weight-GEMM mapping (M=32 x N=16)
  const int wqm = (warp & 1) << 5;
  const int wqn = (warp >> 1) << 4;
  const int ntb = (warp >> 1) << 1;
  const int r0q = wqm + lm;
  const int cg  = warp >> 1;
  const int kp0 = (wqn >> 1) + tig;
  const int pairbar = 1 + (warp & 3) + (hh << 2);   // named barrier id 1..8
  const int halfbar = 9 + (warp & 1);               // half-CTA barrier id 9/10

  if (tid < N) {
    s.mrow[tid] = (g_mask[b * N + tid] != 0) ? 1.f : 0.f;
    s.coords[tid][0] = g_coords[(b * N + tid) * 3 + 0];
    s.coords[tid][1] = g_coords[(b * N + tid) * 3 + 1];
    s.coords[tid][2] = g_coords[(b * N + tid) * 3 + 2];
  }
  if (tid >= 64 && tid < 64 + 42)
    ((float*)s.Wel)[tid - 64] = g_We[tid - 64];
  for (int i = tid; i < 3 * F; i += TPB)
    ((float*)s.bf_all)[i] = g_bf[i];

  // ---- initial h: registers + one smem copy + LN partials ----
  float hv[4][4];
#pragma unroll
  for (int rt = 0; rt < 2; ++rt)
#pragma unroll
    for (int tq = 0; tq < 2; ++tq) {
      const int u = rt * 2 + tq;
      const int rA2 = wqm + rt * 16 + lm, rB2 = rA2 + 8;
      const int c2 = wqn + tq * 8 + 2 * tig;
      const int mA = g_mask[b * N + rA2], mB = g_mask[b * N + rB2];
      const int sA = g_species[b * N + rA2] - 1;
      const int sB = g_species[b * N + rB2] - 1;
      float2 eA = *(const float2*)&g_embed[sA * F + c2];
      float2 eB = *(const float2*)&g_embed[sB * F + c2];
      hv[u][0] = mA ? eA.x : 0.f;  hv[u][1] = mA ? eA.y : 0.f;
      hv[u][2] = mB ? eB.x : 0.f;  hv[u][3] = mB ? eB.y : 0.f;
      *(float2*)&s.h[rA2][c2] = make_float2(hv[u][0], hv[u][1]);
      *(float2*)&s.h[rB2][c2] = make_float2(hv[u][2], hv[u][3]);
    }
  ln_partials(hv, r0q, cg, tig, s.pS, s.pQ);
  __syncthreads();

  // ldmatrix per-thread geometry
  const int g8 = lane >> 3, r8 = lane & 7;
  const uint32_t aBaseH = s2u(&s.ahp[mb + (g8 & 1) * 8 + r8][(g8 >> 1) * 4]);
  const uint32_t aqBaseH = s2u(&s.ahp[wqm + (g8 & 1) * 8 + r8][(g8 >> 1) * 4]);
  const uint32_t aqBaseL = s2u(&s.alp[wqm + (g8 & 1) * 8 + r8][(g8 >> 1) * 4]);
  const uint32_t RT1 = 16 * APAD * 4;
  // fp16 attention B bases: x4 tile group g8 -> (sub-tile g8>>1, quad g8&1)
  const uint32_t kB2 = s2u(s.u1h)
      + (uint32_t)((((g8 >> 1) * 8 + r8) * APAD) + (g8 & 1) * 4) * 4;
  const uint32_t vB2 = s2u(s.vth)
      + (uint32_t)((((g8 >> 1) * 8 + r8) * TPAD) + (g8 & 1) * 4) * 4;
  const uint32_t atBaseH = s2u(s.u1h)
      + (uint32_t)((hh * 64 + mb + (g8 & 1) * 8 + r8) * TPAD + (g8 >> 1) * 4) * 4;

  float aq[4][4], ak[4][4], av[4][4];

  for (int l = 0; l < 3; ++l) {
    const uint4* __restrict__ wq = g_wfrag + (size_t)(l * 5 + 0) * 4096;
    const uint4* __restrict__ wk = g_wfrag + (size_t)(l * 5 + 1) * 4096;
    const uint4* __restrict__ wv = g_wfrag + (size_t)(l * 5 + 2) * 4096;
    const uint4* __restrict__ wo = g_wfrag + (size_t)(l * 5 + 3) * 4096;
    const uint4* __restrict__ wf = g_wfrag + (size_t)(l * 5 + 4) * 4096;

    // ---- LN(h) from registers -> ahp/alp ----
    ln_pack(hv, r0q, kp0, s.pS, s.pQ, s.ahp, s.alp);
    asm volatile("bar.sync %0, %1;" :: "r"(halfbar), "r"(256) : "memory"); // (1)

    // ---- fused q,k,v GEMM, M=32 x N=16 per warp (split-bf16) ----
#pragma unroll
    for (int u = 0; u < 4; ++u)
#pragma unroll
      for (int i = 0; i < 4; ++i) { aq[u][i] = 0.f; ak[u][i] = 0.f; av[u][i] = 0.f; }
#pragma unroll
    for (int kst = 0; kst < 8; ++kst) {
      uint32_t x0h0, x0h1, x0h2, x0h3, x0l0, x0l1, x0l2, x0l3;
      uint32_t x1h0, x1h1, x1h2, x1h3, x1l0, x1l1, x1l2, x1l3;
      ldsm4(x0h0, x0h1, x0h2, x0h3, aqBaseH + kst * 32);
      ldsm4(x0l0, x0l1, x0l2, x0l3, aqBaseL + kst * 32);
      ldsm4(x1h0, x1h1, x1h2, x1h3, aqBaseH + RT1 + kst * 32);
      ldsm4(x1l0, x1l1, x1l2, x1l3, aqBaseL + RT1 + kst * 32);
      const int fo = kst * 512 + ntb * 32 + lane;
      {
        uint4 f0 = wq[fo], f1 = wq[fo + 32];
        mma3(aq[0], x0h0, x0h1, x0h2, x0h3, x0l0, x0l1, x0l2, x0l3, f0);
        mma3(aq[1], x0h0, x0h1, x0h2, x0h3, x0l0, x0l1, x0l2, x0l3, f1);
        mma3(aq[2], x1h0, x1h1, x1h2, x1h3, x1l0, x1l1, x1l2, x1l3, f0);
        mma3(aq[3], x1h0, x1h1, x1h2, x1h3, x1l0, x1l1, x1l2, x1l3, f1);
      }
      {
        uint4 f0 = wk[fo], f1 = wk[fo + 32];
        mma3(ak[0], x0h0, x0h1, x0h2, x0h3, x0l0, x0l1, x0l2, x0l3, f0);
        mma3(ak[1], x0h0, x0h1, x0h2, x0h3, x0l0, x0l1, x0l2, x0l3, f1);
        mma3(ak[2], x1h0, x1h1, x1h2, x1h3, x1l0, x1l1, x1l2, x1l3, f0);
        mma3(ak[3], x1h0, x1h1, x1h2, x1h3, x1l0, x1l1, x1l2, x1l3, f1);
      }
      {
        uint4 f0 = wv[fo], f1 = wv[fo + 32];
        mma3(av[0], x0h0, x0h1, x0h2, x0h3, x0l0, x0l1, x0l2, x0l3, f0);
        mma3(av[1], x0h0, x0h1, x0h2, x0h3, x0l0, x0l1, x0l2, x0l3, f1);
        mma3(av[2], x1h0, x1h1, x1h2, x1h3, x1l0, x1l1, x1l2, x1l3, f0);
        mma3(av[3], x1h0, x1h1, x1h2, x1h3, x1l0, x1l1, x1l2, x1l3, f1);
      }
    }
    asm volatile("bar.sync %0, %1;" :: "r"(halfbar), "r"(256) : "memory"); // (2)

    // q/k/v packs (fp16, single arrays)
#pragma unroll
    for (int rt = 0; rt < 2; ++rt)
#pragma unroll
      for (int tq = 0; tq < 2; ++tq) {
        const int u = rt * 2 + tq;
        const int rowA = wqm + rt * 16 + lm, rowB = rowA + 8;
        const int kp = (wqn + tq * 8 + 2 * tig) >> 1;
        s.ahp[rowA][kp] = packh2(aq[u][0], aq[u][1]);
        s.ahp[rowB][kp] = packh2(aq[u][2], aq[u][3]);
        s.u1h[rowA * APAD + kp] = packh2(ak[u][0], ak[u][1]);
        s.u1h[rowB * APAD + kp] = packh2(ak[u][2], ak[u][3]);
        const int c = wqn + tq * 8 + 2 * tig;
        const int mbv = wqm + rt * 16;
        float p0 = __shfl_xor_sync(0xffffffffu, av[u][0], 4);
        float p1 = __shfl_xor_sync(0xffffffffu, av[u][1], 4);
        float p2 = __shfl_xor_sync(0xffffffffu, av[u][2], 4);
        float p3 = __shfl_xor_sync(0xffffffffu, av[u][3], 4);
        if ((lm & 1) == 0) {
          int mp = (mbv + lm) >> 1;
          s.vth[c][mp]     = packh2(av[u][0], p0);
          s.vth[c + 1][mp] = packh2(av[u][1], p1);
        } else {
          int mp = (mbv + lm + 7) >> 1;
          s.vth[c][mp]     = packh2(p2, av[u][2]);
          s.vth[c + 1][mp] = packh2(p3, av[u][3]);
        }
      }
    __syncthreads();                                           // (3) FULL

    // ---- logits = q @ k^T (fp16 single-mma; head hh, m-half mblk) ----
#pragma unroll
    for (int t = 0; t < 4; ++t)
#pragma unroll
      for (int i = 0; i < 4; ++i) aq[t][i] = 0.f;
#pragma unroll
    for (int ks = 0; ks < 4; ++ks) {
      uint32_t ah0, ah1, ah2, ah3;
      ldsm4(ah0, ah1, ah2, ah3, aBaseH + (uint32_t)(hh * 32 + ks * 8) * 4);
#pragma unroll
      for (int tp = 0; tp < 2; ++tp) {
        uint32_t b0e, b1e, b0o, b1o;
        ldsm4(b0e, b1e, b0o, b1o,
              kB2 + (uint32_t)((mblk * 32 + tp * 16) * APAD + hh * 32 + ks * 8) * 4);
        mma_f16(aq[tp * 2],     ah0, ah1, ah2, ah3, b0e, b1e);
        mma_f16(aq[tp * 2 + 1], ah0, ah1, ah2, ah3, b0o, b1o);
      }
    }

    // ---- epilogue: unified bias + mask + 1-barrier softmax -> attn ----
    {
      float2 pbA[4], pbB[4];
      if (l == 0) {
        const float w0 = s.Wel[0][0][hh], w1 = s.Wel[0][1][hh], w2 = s.Wel[0][2][hh],
                    w3 = s.Wel[0][3][hh], w4 = s.Wel[0][4][hh], w5 = s.Wel[0][5][hh],
                    w6 = s.Wel[0][6][hh];
        const float u0 = s.Wel[1][0][hh], u1 = s.Wel[1][1][hh], u2 = s.Wel[1][2][hh],
                    u3 = s.Wel[1][3][hh], u4 = s.Wel[1][4][hh], u5 = s.Wel[1][5][hh],
                    u6 = s.Wel[1][6][hh];
        const float v0 = s.Wel[2][0][hh], v1 = s.Wel[2][1][hh], v2 = s.Wel[2][2][hh],
                    v3 = s.Wel[2][3][hh], v4 = s.Wel[2][4][hh], v5 = s.Wel[2][5][hh],
                    v6 = s.Wel[2][6][hh];
        const bool okA = s.mrow[rA] > 0.f, okB = s.mrow[rB] > 0.f;
        const float a0 = s.coords[rA][0], a1 = s.coords[rA][1], a2 = s.coords[rA][2];
        const float b0 = s.coords[rB][0], b1 = s.coords[rB][1], b2 = s.coords[rB][2];
#pragma unroll
        for (int t = 0; t < 4; ++t) {
          float b0A[2], b1A[2], b2A[2], b0B[2], b1B[2], b2B[2];
#pragma unroll
          for (int j = 0; j < 2; ++j) {
            const int m = mblk * 32 + t * 8 + 2 * tig + j;
            const float m0 = s.coords[m][0], m1 = s.coords[m][1], m2 = s.coords[m][2];
            const bool okm = s.mrow[m] > 0.f;
            {
              float dx = a0 - m0, dy = a1 - m1, dz = a2 - m2;
              float d = sqrtf(dx * dx + dy * dy + dz * dz + 1e-12f);
              float g1 = 1.f / (1.f + __expf(2.f - d));
              float g2 = 1.f / (1.f + __expf(4.f - d));
              float g3 = 1.f / (1.f + __expf(6.f - d));
              bool ok = okA && okm;
              b0A[j] = ok ? dx * w0 + dy * w1 + dz * w2 + d * w3
                          + g1 * w4 + g2 * w5 + g3 * w6 : NEGV;
              b1A[j] = ok ? dx * u0 + dy * u1 + dz * u2 + d * u3
                          + g1 * u4 + g2 * u5 + g3 * u6 : NEGV;
              b2A[j] = ok ? dx * v0 + dy * v1 + dz * v2 + d * v3
                          + g1 * v4 + g2 * v5 + g3 * v6 : NEGV;
            }
            {
              float dx = b0 - m0, dy = b1 - m1, dz = b2 - m2;
              float d = sqrtf(dx * dx + dy * dy + dz * dz + 1e-12f);
              float g1 = 1.f / (1.f + __expf(2.f - d));
              float g2 = 1.f / (1.f + __expf(4.f - d));
              float g3 = 1.f / (1.f + __expf(6.f - d));
              bool ok = okB && okm;
              b0B[j] = ok ? dx * w0 + dy * w1 + dz * w2 + d * w3
                          + g1 * w4 + g2 * w5 + g3 * w6 : NEGV;
              b1B[j] = ok ? dx * u0 + dy * u1 + dz * u2 + d * u3
                          + g1 * u4 + g2 * u5 + g3 * u6 : NEGV;
              b2B[j] = ok ? dx * v0 + dy * v1 + dz * v2 + d * v3
                          + g1 * v4 + g2 * v5 + g3 * v6 : NEGV;
            }
          }
          const int m0i = mblk * 32 + t * 8 + 2 * tig;
          pbA[t] = make_float2(b0A[0], b0A[1]);
          pbB[t] = make_float2(b0B[0], b0B[1]);
          *(float2*)&s.bias12[0][hh][rA][m0i] = make_float2(b1A[0], b1A[1]);
          *(float2*)&s.bias12[1][hh][rA][m0i] = make_float2(b2A[0], b2A[1]);
          *(float2*)&s.bias12[0][hh][rB][m0i] = make_float2(b1B[0], b1B[1]);
          *(float2*)&s.bias12[1][hh][rB][m0i] = make_float2(b2B[0], b2B[1]);
        }
      } else {
        const float* bA = &s.bias12[l - 1][hh][rA][0];
        const float* bB = &s.bias12[l - 1][hh][rB][0];
#pragma unroll
        for (int t = 0; t < 4; ++t) {
          const int m0i = mblk * 32 + t * 8 + 2 * tig;
          pbA[t] = *(const float2*)&bA[m0i];
          pbB[t] = *(const float2*)&bB[m0i];
        }
      }
      float xA[8], xB[8];
#pragma unroll
      for (int t = 0; t < 4; ++t) {
        xA[2 * t]     = aq[t][0] * INV_SQRT_DH + pbA[t].x;
        xA[2 * t + 1] = aq[t][1] * INV_SQRT_DH + pbA[t].y;
        xB[2 * t]     = aq[t][2] * INV_SQRT_DH + pbB[t].x;
        xB[2 * t + 1] = aq[t][3] * INV_SQRT_DH + pbB[t].y;
      }
      float mxA = xA[0], mxB = xB[0];
#pragma unroll
      for (int i = 1; i < 8; ++i) { mxA = fmaxf(mxA, xA[i]); mxB = fmaxf(mxB, xB[i]); }
      mxA = fmaxf(mxA, __shfl_xor_sync(0xffffffffu, mxA, 1));
      mxA = fmaxf(mxA, __shfl_xor_sync(0xffffffffu, mxA, 2));
      mxB = fmaxf(mxB, __shfl_xor_sync(0xffffffffu, mxB, 1));
      mxB = fmaxf(mxB, __shfl_xor_sync(0xffffffffu, mxB, 2));
      float smA = 0.f, smB = 0.f;
#pragma unroll
      for (int i = 0; i < 8; ++i) {
        xA[i] = __expf(xA[i] - mxA); smA += xA[i];
        xB[i] = __expf(xB[i] - mxB); smB += xB[i];
      }
      smA += __shfl_xor_sync(0xffffffffu, smA, 1);
      smA += __shfl_xor_sync(0xffffffffu, smA, 2);
      smB += __shfl_xor_sync(0xffffffffu, smB, 1);
      smB += __shfl_xor_sync(0xffffffffu, smB, 2);
      if (tig == 0) {
        s.rmx[hh][rA][mblk] = mxA;  s.rsm[hh][rA][mblk] = smA;
        s.rmx[hh][rB][mblk] = mxB;  s.rsm[hh][rB][mblk] = smB;
      }
      __syncthreads();   // (4) FULL: k-region alias across heads + partials
      float mA0 = s.rmx[hh][rA][0], mA1 = s.rmx[hh][rA][1];
      float gA = fmaxf(mA0, mA1);
      float dA = s.rsm[hh][rA][0] * __expf(mA0 - gA)
               + s.rsm[hh][rA][1] * __expf(mA1 - gA);
      float mB0 = s.rmx[hh][rB][0], mB1 = s.rmx[hh][rB][1];
      float gB = fmaxf(mB0, mB1);
      float dB = s.rsm[hh][rB][0] * __expf(mB0 - gB)
               + s.rsm[hh][rB][1] * __expf(mB1 - gB);
      const float scA = __expf(mxA - gA) / dA;
      const float scB = __expf(mxB - gB) / dB;
      const int baseA = (hh * 64 + rA) * TPAD;
      const int baseB = (hh * 64 + rB) * TPAD;
#pragma unroll
      for (int t = 0; t < 4; ++t) {
        int mp = mblk * 16 + t * 4 + tig;
        s.u1h[baseA + mp] = packh2(xA[2 * t] * scA, xA[2 * t + 1] * scA);
        s.u1h[baseB + mp] = packh2(xB[2 * t] * scB, xB[2 * t + 1] * scB);
      }
    }
    // (5) pair barrier: attn rows for (hh, mb-block) produced/consumed by this
    // warp pair only (mblk 0/1); vth was fenced at (3).
    asm volatile("bar.sync %0, %1;" :: "r"(pairbar), "r"(64) : "memory");

    // ---- msg = attn @ v (fp16 single-mma) -> pack split-bf16 into ahp/alp ----
#pragma unroll
    for (int t = 0; t < 4; ++t)
#pragma unroll
      for (int i = 0; i < 4; ++i) aq[t][i] = 0.f;
    {
      const int dhb = mblk * 32;
#pragma unroll
      for (int ks = 0; ks < 4; ++ks) {
        uint32_t ah0, ah1, ah2, ah3;
        ldsm4(ah0, ah1, ah2, ah3, atBaseH + (uint32_t)(ks * 8) * 4);
#pragma unroll
        for (int tp = 0; tp < 2; ++tp) {
          uint32_t b0e, b1e, b0o, b1o;
          ldsm4(b0e, b1e, b0o, b1o,
                vB2 + (uint32_t)((hh * 64 + dhb + tp * 16) * TPAD + ks * 8) * 4);
          mma_f16(aq[tp * 2],     ah0, ah1, ah2, ah3, b0e, b1e);
          mma_f16(aq[tp * 2 + 1], ah0, ah1, ah2, ah3, b0o, b1o);
        }
      }
#pragma unroll
      for (int t = 0; t < 4; ++t) {
        int kp = hh * 32 + (dhb >> 1) + t * 4 + tig;
        pack2(aq[t][0], aq[t][1], &s.ahp[rA][kp], &s.alp[rA][kp]);
        pack2(aq[t][2], aq[t][3], &s.ahp[rB][kp], &s.alp[rB][kp]);
      }
    }
    __syncthreads();                                           // (6) FULL

    // ---- h += msg @ Wo (M=32 x N=16 mapping) ----
#pragma unroll
    for (int u = 0; u < 4; ++u)
#pragma unroll
      for (int i = 0; i < 4; ++i) ak[u][i] = 0.f;
#pragma unroll
    for (int kst = 0; kst < 8; ++kst) {
      uint32_t x0h0, x0h1, x0h2, x0h3, x0l0, x0l1, x0l2, x0l3;
      uint32_t x1h0, x1h1, x1h2, x1h3, x1l0, x1l1, x1l2, x1l3;
      ldsm4(x0h0, x0h1, x0h2, x0h3, aqBaseH + kst * 32);
      ldsm4(x0l0, x0l1, x0l2, x0l3, aqBaseL + kst * 32);
      ldsm4(x1h0, x1h1, x1h2, x1h3, aqBaseH + RT1 + kst * 32);
      ldsm4(x1l0, x1l1, x1l2, x1l3, aqBaseL + RT1 + kst * 32);
      const int fo = kst * 512 + ntb * 32 + lane;
      uint4 f0 = wo[fo], f1 = wo[fo + 32];
      mma3(ak[0], x0h0, x0h1, x0h2, x0h3, x0l0, x0l1, x0l2, x0l3, f0);
      mma3(ak[1], x0h0, x0h1, x0h2, x0h3, x0l0, x0l1, x0l2, x0l3, f1);
      mma3(ak[2], x1h0, x1h1, x1h2, x1h3, x1l0, x1l1, x1l2, x1l3, f0);
      mma3(ak[3], x1h0, x1h1, x1h2, x1h3, x1l0, x1l1, x1l2, x1l3, f1);
    }
    // Wo epilogue: h -> registers; LN partials
#pragma unroll
    for (int rt = 0; rt < 2; ++rt)
#pragma unroll
      for (int tq = 0; tq < 2; ++tq) {
        const int u = rt * 2 + tq;
        const int rA2 = wqm + rt * 16 + lm, rB2 = rA2 + 8;
        const int c2 = wqn + tq * 8 + 2 * tig;
        float2 h0 = *(float2*)&s.h[rA2][c2];
        hv[u][0] = h0.x + ak[u][0];  hv[u][1] = h0.y + ak[u][1];
        float2 h1 = *(float2*)&s.h[rB2][c2];
        hv[u][2] = h1.x + ak[u][2];  hv[u][3] = h1.y + ak[u][3];
      }
    ln_partials(hv, r0q, cg, tig, s.pS, s.pQ);
    asm volatile("bar.sync %0, %1;" :: "r"(halfbar), "r"(256) : "memory"); // (7)

    // ---- LN(h) from registers -> ahp/alp ----
    ln_pack(hv, r0q, kp0, s.pS, s.pQ, s.ahp, s.alp);
    asm volatile("bar.sync %0, %1;" :: "r"(halfbar), "r"(256) : "memory"); // (8)

    // ---- Wf GEMM (M=32 x N=16) ----
#pragma unroll
    for (int u = 0; u < 4; ++u)
#pragma unroll
      for (int i = 0; i < 4; ++i) ak[u][i] = 0.f;
#pragma unroll
    for (int kst = 0; kst < 8; ++kst) {
      uint32_t x0h0, x0h1, x0h2, x0h3, x0l0, x0l1, x0l2, x0l3;
      uint32_t x1h0, x1h1, x1h2, x1h3, x1l0, x1l1, x1l2, x1l3;
      ldsm4(x0h0, x0h1, x0h2, x0h3, aqBaseH + kst * 32);
      ldsm4(x0l0, x0l1, x0l2, x0l3, aqBaseL + kst * 32);
      ldsm4(x1h0, x1h1, x1h2, x1h3, aqBaseH + RT1 + kst * 32);
      ldsm4(x1l0, x1l1, x1l2, x1l3, aqBaseL + RT1 + kst * 32);
      const int fo = kst * 512 + ntb * 32 + lane;
      uint4 f0 = wf[fo], f1 = wf[fo + 32];
      mma3(ak[0], x0h0, x0h1, x0h2, x0h3, x0l0, x0l1, x0l2, x0l3, f0);
      mma3(ak[1], x0h0, x0h1, x0h2, x0h3, x0l0, x0l1, x0l2, x0l3, f1);
      mma3(ak[2], x1h0, x1h1, x1h2, x1h3, x1l0, x1l1, x1l2, x1l3, f0);
      mma3(ak[3], x1h0, x1h1, x1h2, x1h3, x1l0, x1l1, x1l2, x1l3, f1);
    }
    // Wf epilogue: finalize h in registers; store to smem; LN partials
#pragma unroll
    for (int rt = 0; rt < 2; ++rt)
#pragma unroll
      for (int tq = 0; tq < 2; ++tq) {
        const int u = rt * 2 + tq;
        const int rA2 = wqm + rt * 16 + lm, rB2 = rA2 + 8;
        const int c2 = wqn + tq * 8 + 2 * tig;
        float mr0 = s.mrow[rA2], mr1 = s.mrow[rB2];
        hv[u][0] = (hv[u][0] + tanhf(ak[u][0] + s.bf_all[l][c2]))     * mr0;
        hv[u][1] = (hv[u][1] + tanhf(ak[u][1] + s.bf_all[l][c2 + 1])) * mr0;
        hv[u][2] = (hv[u][2] + tanhf(ak[u][2] + s.bf_all[l][c2]))     * mr1;
        hv[u][3] = (hv[u][3] + tanhf(ak[u][3] + s.bf_all[l][c2 + 1])) * mr1;
        *(float2*)&s.h[rA2][c2] = make_float2(hv[u][0], hv[u][1]);
        *(float2*)&s.h[rB2][c2] = make_float2(hv[u][2], hv[u][3]);
      }
    ln_partials(hv, r0q, cg, tig, s.pS, s.pQ);
    asm volatile("bar.sync %0, %1;" :: "r"(halfbar), "r"(256) : "memory"); // (9)
  }

  // ---- final layernorm from registers -> global output ----
#pragma unroll
  for (int rr = 0; rr < 4; ++rr) {
    const int r = r0q + rr * 8;
    float4 sa = *(const float4*)&s.pS[r][0];
    float4 sb = *(const float4*)&s.pS[r][4];
    float sum = ((sa.x + sa.y) + (sa.z + sa.w)) + ((sb.x + sb.y) + (sb.z + sb.w));
    float4 qa = *(const float4*)&s.pQ[r][0];
    float4 qb = *(const float4*)&s.pQ[r][4];
    float qs = ((qa.x + qa.y) + (qa.z + qa.w)) + ((qb.x + qb.y) + (qb.z + qb.w));
    float mean = sum * (1.f / 128.f);
    float var = qs * (1.f / 128.f) - mean * mean;
    float inv = rsqrtf(var + 1e-5f);
    const int ub = (rr >> 1) * 2;
    const int ib = (rr & 1) * 2;
    float* orow = g_out + ((size_t)(b * N + r)) * F;
    const int cA = wqn + 2 * tig;
    *(float2*)&orow[cA] = make_float2((hv[ub][ib] - mean) * inv,
                                      (hv[ub][ib + 1] - mean) * inv);
    *(float2*)&orow[cA + 8] = make_float2((hv[ub + 1][ib] - mean) * inv,
                                          (hv[ub + 1][ib + 1] - mean) * inv);
  }
}

// Split + fragment-order all 15 weight matrices.
__global__ void prep_weights(const float* __restrict__ Wq,
                             const float* __restrict__ Wk,
                             const float* __restrict__ Wv,
                             const float* __restrict__ Wo,
                             const float* __restrict__ Wf)
{
  int idx = blockIdx.x * blockDim.x + threadIdx.x;
  if (idx >= 15 * 8 * 16 * 32) return;
  int mat   = idx >> 12;
  int kst   = (idx >> 9) & 7;
  int ntile = (idx >> 5) & 15;
  int lane  = idx & 31;
  int l = mat / 5, which = mat % 5;
  const float* W =
      (which == 0 ? Wq : which == 1 ? Wk : which == 2 ? Wv : which == 3 ? Wo : Wf)
      + l * F * F;
  int n   = ntile * 8 + (lane >> 2);
  int kpA = kst * 8 + (lane & 3);
  int kpB = kpA + 4;

  float a0 = W[(2 * kpA)     * F + n];
  float a1 = W[(2 * kpA + 1) * F + n];
  float c0 = W[(2 * kpB)     * F + n];
  float c1 = W[(2 * kpB + 1) * F + n];

  __nv_bfloat162 ha = __floats2bfloat162_rn(a0, a1);
  __nv_bfloat162 la = __floats2bfloat162_rn(a0 - __bfloat162float(ha.x),
                                            a1 - __bfloat162float(ha.y));
  __nv_bfloat162 hc = __floats2bfloat162_rn(c0, c1);
  __nv_bfloat162 lc = __floats2bfloat162_rn(c0 - __bfloat162float(hc.x),
                                            c1 - __bfloat162float(hc.y));
  uint4 w;
  w.x = *reinterpret_cast<uint32_t*>(&ha);
  w.y = *reinterpret_cast<uint32_t*>(&hc);
  w.z = *reinterpret_cast<uint32_t*>(&la);
  w.w = *reinterpret_cast<uint32_t*>(&lc);
  g_wfrag[idx] = w;
}

}  // namespace

extern "C" void kernel_launch(void* const* d_in, const int* in_sizes, int n_in,
                              void* d_out, int out_size)
{
  (void)n_in; (void)out_size;
  const float* coords  = (const float*)d_in[0];
  const int*   species = (const int*)d_in[1];
  const int*   mask    = (const int*)d_in[2];
  const float* embed   = (const float*)d_in[3];
  const float* Wq      = (const float*)d_in[4];
  const float* Wk      = (const float*)d_in[5];
  const float* Wv      = (const float*)d_in[6];
  const float* Wo      = (const float*)d_in[7];
  const float* We      = (const float*)d_in[8];
  const float* Wf      = (const float*)d_in[9];
  const float* bf      = (const float*)d_in[10];

  const int B = in_sizes[0] / (N * 3);   // 2048

  prep_weights<<<(15 * 8 * 16 * 32 + 255) / 256, 256>>>(Wq, Wk, Wv, Wo, Wf);

  cudaFuncSetAttribute(gnn_kernel, cudaFuncAttributeMaxDynamicSharedMemorySize,
                       (int)sizeof(Smem));
  gnn_kernel<<<B, TPB, sizeof(Smem)>>>(coords, species, mask, embed,
                                       We, bf, (float*)d_out);
}

// round 17
// speedup vs baseline: 1.1002x; 1.1002x over previous
#include <cuda_runtime.h>
#include <cuda_bf16.h>
#include <cuda_fp16.h>
#include <stdint.h>
#include <math.h>

#define TPB 256

namespace {

constexpr int N = 64;
constexpr int F = 128;
constexpr int APAD = 68;   // [n][kpair] packed stride (A ops, q, k)
constexpr int TPAD = 36;   // [dh][mpair] & [hh][n][mpair] stride
constexpr float NEGV = -1e9f;
constexpr float INV_SQRT_DH = 0.125f;

// Fragment-ordered split weights: [15 mats][kstep 8][ntile 16][lane 32] x uint4
__device__ uint4 g_wfrag[15 * 8 * 16 * 32];

struct __align__(16) Smem {
  float h[N][F];                         // residual
  uint32_t ahp[N][APAD], alp[N][APAD];   // LN(h)/msg split-bf16; q fp16 (ahp only)
  uint32_t u1h[4608];                    // k fp16 [m][APAD] then attn fp16 [hh*64+n][TPAD]
  uint32_t vth[F][TPAD];                 // v fp16 transposed [dh][mpair]
  float coords[N][3];
  float mrow[N];
  float bf_all[3][F];
  float Wel[3][7][2];
};                                       // ~105 KB -> 2 CTAs/SM

__device__ __forceinline__ void mma_bf16(float* d,
    uint32_t a0, uint32_t a1, uint32_t a2, uint32_t a3,
    uint32_t b0, uint32_t b1)
{
  asm volatile(
    "mma.sync.aligned.m16n8k16.row.col.f32.bf16.bf16.f32 "
    "{%0,%1,%2,%3}, {%4,%5,%6,%7}, {%8,%9}, {%0,%1,%2,%3};\n"
    : "+f"(d[0]), "+f"(d[1]), "+f"(d[2]), "+f"(d[3])
    : "r"(a0), "r"(a1), "r"(a2), "r"(a3), "r"(b0), "r"(b1));
}

__device__ __forceinline__ void mma_f16(float* d,
    uint32_t a0, uint32_t a1, uint32_t a2, uint32_t a3,
    uint32_t b0, uint32_t b1)
{
  asm volatile(
    "mma.sync.aligned.m16n8k16.row.col.f32.f16.f16.f32 "
    "{%0,%1,%2,%3}, {%4,%5,%6,%7}, {%8,%9}, {%0,%1,%2,%3};\n"
    : "+f"(d[0]), "+f"(d[1]), "+f"(d[2]), "+f"(d[3])
    : "r"(a0), "r"(a1), "r"(a2), "r"(a3), "r"(b0), "r"(b1));
}

__device__ __forceinline__ void mma3(float* d,
    uint32_t ah0, uint32_t ah1, uint32_t ah2, uint32_t ah3,
    uint32_t al0, uint32_t al1, uint32_t al2, uint32_t al3,
    uint4 w)
{
  mma_bf16(d, ah0, ah1, ah2, ah3, w.x, w.y);
  mma_bf16(d, ah0, ah1, ah2, ah3, w.z, w.w);
  mma_bf16(d, al0, al1, al2, al3, w.x, w.y);
}

__device__ __forceinline__ void ldsm4(uint32_t& r0, uint32_t& r1,
                                      uint32_t& r2, uint32_t& r3, uint32_t a)
{
  asm volatile("ldmatrix.sync.aligned.m8n8.x4.shared.b16 {%0,%1,%2,%3}, [%4];"
               : "=r"(r0), "=r"(r1), "=r"(r2), "=r"(r3) : "r"(a));
}

__device__ __forceinline__ void pack2(float x, float y,
                                      uint32_t* hp, uint32_t* lp)
{
  __nv_bfloat162 h2 = __floats2bfloat162_rn(x, y);
  float hx = __bfloat162float(h2.x), hy = __bfloat162float(h2.y);
  __nv_bfloat162 l2 = __floats2bfloat162_rn(x - hx, y - hy);
  *hp = *reinterpret_cast<uint32_t*>(&h2);
  *lp = *reinterpret_cast<uint32_t*>(&l2);
}

__device__ __forceinline__ uint32_t packh2(float x, float y)
{
  __half2 h = __floats2half2_rn(x, y);
  return *reinterpret_cast<uint32_t*>(&h);
}

__device__ __forceinline__ uint32_t s2u(const void* p) {
  return (uint32_t)__cvta_generic_to_shared(p);
}

// Full-row LN from smem h, split-packed into ahp/alp. 8 warps, rows stride 8.
__device__ __forceinline__ void ln_split8(const float (*src)[F],
    uint32_t (*ahp)[APAD], uint32_t (*alp)[APAD], int tid)
{
  const int w = tid >> 5, l = tid & 31;
  for (int n = w; n < N; n += 8) {
    float2 p0 = *(const float2*)&src[n][2 * l];
    float2 p1 = *(const float2*)&src[n][64 + 2 * l];
    float sm = p0.x + p0.y + p1.x + p1.y;
#pragma unroll
    for (int o = 16; o; o >>= 1) sm += __shfl_xor_sync(0xffffffffu, sm, o);
    float mean = sm * (1.f / 128.f);
    float d0 = p0.x - mean, d1 = p0.y - mean, d2 = p1.x - mean, d3 = p1.y - mean;
    float ss = d0 * d0 + d1 * d1 + d2 * d2 + d3 * d3;
#pragma unroll
    for (int o = 16; o; o >>= 1) ss += __shfl_xor_sync(0xffffffffu, ss, o);
    float inv = rsqrtf(ss * (1.f / 128.f) + 1e-5f);
    d0 *= inv; d1 *= inv; d2 *= inv; d3 *= inv;
    pack2(d0, d1, &ahp[n][l],      &alp[n][l]);
    pack2(d2, d3, &ahp[n][l + 32], &alp[n][l + 32]);
  }
}

__global__ void __launch_bounds__(TPB, 2) gnn_kernel(
    const float* __restrict__ g_coords,
    const int*   __restrict__ g_species,
    const int*   __restrict__ g_mask,
    const float* __restrict__ g_embed,
    const float* __restrict__ g_We,
    const float* __restrict__ g_bf,
    float* __restrict__ g_out)
{
  extern __shared__ unsigned char smem_raw[];
  Smem& s = *reinterpret_cast<Smem*>(smem_raw);
  const int b = blockIdx.x;
  const int tid = threadIdx.x;

  const int warp = tid >> 5, lane = tid & 31;   // 8 warps
  // attention mapping: warp = (hh, mb); full m per warp (warp-local softmax)
  const int mb = (warp & 3) << 4;
  const int hh = warp >> 2;
  const int lm = lane >> 2, tig = lane & 3;
  const int rA = mb + lm, rB = mb + lm + 8;
  // weight-GEMM mapping: M32 x N16, 2 column passes per warp
  const int wqm  = (warp & 1) << 5;
  const int wqnB = (warp >> 1) << 4;            // pass-0 col base (0..48)

  if (tid < N) {
    s.mrow[tid] = (g_mask[b * N + tid] != 0) ? 1.f : 0.f;
    s.coords[tid][0] = g_coords[(b * N + tid) * 3 + 0];
    s.coords[tid][1] = g_coords[(b * N + tid) * 3 + 1];
    s.coords[tid][2] = g_coords[(b * N + tid) * 3 + 2];
  }
  if (tid >= 64 && tid < 64 + 42)
    ((float*)s.Wel)[tid - 64] = g_We[tid - 64];
  for (int i = tid; i < 3 * F; i += TPB)
    ((float*)s.bf_all)[i] = g_bf[i];
  for (int i = tid; i < N * F; i += TPB) {
    int n = i >> 7, f = i & (F - 1);
    int sp = g_species[b * N + n] - 1;
    float hv = g_embed[sp * F + f];
    s.h[n][f] = (g_mask[b * N + n] != 0) ? hv : 0.f;
  }
  __syncthreads();

  // ldmatrix per-thread geometry
  const int g8 = lane >> 3, r8 = lane & 7;
  const uint32_t aqBaseH = s2u(&s.ahp[wqm + (g8 & 1) * 8 + r8][(g8 >> 1) * 4]);
  const uint32_t aqBaseL = s2u(&s.alp[wqm + (g8 & 1) * 8 + r8][(g8 >> 1) * 4]);
  const uint32_t aBaseH  = s2u(&s.ahp[mb + (g8 & 1) * 8 + r8][(g8 >> 1) * 4]);
  const uint32_t RT1 = 16 * APAD * 4;
  const uint32_t kB2 = s2u(s.u1h)
      + (uint32_t)((((g8 >> 1) * 8 + r8) * APAD) + (g8 & 1) * 4) * 4;
  const uint32_t vB2 = s2u(s.vth)
      + (uint32_t)((((g8 >> 1) * 8 + r8) * TPAD) + (g8 & 1) * 4) * 4;
  const uint32_t atBaseH = s2u(s.u1h)
      + (uint32_t)((hh * 64 + mb + (g8 & 1) * 8 + r8) * TPAD + (g8 >> 1) * 4) * 4;

  for (int l = 0; l < 3; ++l) {
    const uint4* __restrict__ wq = g_wfrag + (size_t)(l * 5 + 0) * 4096;
    const uint4* __restrict__ wk = g_wfrag + (size_t)(l * 5 + 1) * 4096;
    const uint4* __restrict__ wv = g_wfrag + (size_t)(l * 5 + 2) * 4096;
    const uint4* __restrict__ wo = g_wfrag + (size_t)(l * 5 + 3) * 4096;
    const uint4* __restrict__ wf = g_wfrag + (size_t)(l * 5 + 4) * 4096;

    // ---- LN(h) -> ahp/alp ----
    ln_split8(s.h, s.ahp, s.alp, tid);
    __syncthreads();                                           // (1)

    // ---- k+v fused GEMM, 2 column passes ----
#pragma unroll
    for (int p = 0; p < 2; ++p) {
      const int wqnp = wqnB + p * 64;
      const int ntbp = ((warp >> 1) + p * 4) << 1;
      float ak[4][4], av[4][4];
#pragma unroll
      for (int u = 0; u < 4; ++u)
#pragma unroll
        for (int i = 0; i < 4; ++i) { ak[u][i] = 0.f; av[u][i] = 0.f; }
#pragma unroll
      for (int kst = 0; kst < 8; ++kst) {
        uint32_t x0h0, x0h1, x0h2, x0h3, x0l0, x0l1, x0l2, x0l3;
        uint32_t x1h0, x1h1, x1h2, x1h3, x1l0, x1l1, x1l2, x1l3;
        ldsm4(x0h0, x0h1, x0h2, x0h3, aqBaseH + kst * 32);
        ldsm4(x0l0, x0l1, x0l2, x0l3, aqBaseL + kst * 32);
        ldsm4(x1h0, x1h1, x1h2, x1h3, aqBaseH + RT1 + kst * 32);
        ldsm4(x1l0, x1l1, x1l2, x1l3, aqBaseL + RT1 + kst * 32);
        const int fo = kst * 512 + ntbp * 32 + lane;
        {
          uint4 f0 = wk[fo], f1 = wk[fo + 32];
          mma3(ak[0], x0h0, x0h1, x0h2, x0h3, x0l0, x0l1, x0l2, x0l3, f0);
          mma3(ak[1], x0h0, x0h1, x0h2, x0h3, x0l0, x0l1, x0l2, x0l3, f1);
          mma3(ak[2], x1h0, x1h1, x1h2, x1h3, x1l0, x1l1, x1l2, x1l3, f0);
          mma3(ak[3], x1h0, x1h1, x1h2, x1h3, x1l0, x1l1, x1l2, x1l3, f1);
        }
        {
          uint4 f0 = wv[fo], f1 = wv[fo + 32];
          mma3(av[0], x0h0, x0h1, x0h2, x0h3, x0l0, x0l1, x0l2, x0l3, f0);
          mma3(av[1], x0h0, x0h1, x0h2, x0h3, x0l0, x0l1, x0l2, x0l3, f1);
          mma3(av[2], x1h0, x1h1, x1h2, x1h3, x1l0, x1l1, x1l2, x1l3, f0);
          mma3(av[3], x1h0, x1h1, x1h2, x1h3, x1l0, x1l1, x1l2, x1l3, f1);
        }
      }
      // pack k, v for this pass (consumed only after sync (3))
#pragma unroll
      for (int rt = 0; rt < 2; ++rt)
#pragma unroll
        for (int tq = 0; tq < 2; ++tq) {
          const int u = rt * 2 + tq;
          const int rowA = wqm + rt * 16 + lm, rowB = rowA + 8;
          const int kp = (wqnp + tq * 8 + 2 * tig) >> 1;
          s.u1h[rowA * APAD + kp] = packh2(ak[u][0], ak[u][1]);
          s.u1h[rowB * APAD + kp] = packh2(ak[u][2], ak[u][3]);
          const int c = wqnp + tq * 8 + 2 * tig;
          const int mbv = wqm + rt * 16;
          float p0 = __shfl_xor_sync(0xffffffffu, av[u][0], 4);
          float p1 = __shfl_xor_sync(0xffffffffu, av[u][1], 4);
          float p2 = __shfl_xor_sync(0xffffffffu, av[u][2], 4);
          float p3 = __shfl_xor_sync(0xffffffffu, av[u][3], 4);
          if ((lm & 1) == 0) {
            int mp = (mbv + lm) >> 1;
            s.vth[c][mp]     = packh2(av[u][0], p0);
            s.vth[c + 1][mp] = packh2(av[u][1], p1);
          } else {
            int mp = (mbv + lm + 7) >> 1;
            s.vth[c][mp]     = packh2(p2, av[u][2]);
            s.vth[c + 1][mp] = packh2(p3, av[u][3]);
          }
        }
    }

    // ---- q GEMM, 2 passes, accs held across barrier ----
    float q0[4][4], q1[4][4];
#pragma unroll
    for (int p = 0; p < 2; ++p) {
      float (*qa)[4] = p ? q1 : q0;
      const int ntbp = ((warp >> 1) + p * 4) << 1;
#pragma unroll
      for (int u = 0; u < 4; ++u)
#pragma unroll
        for (int i = 0; i < 4; ++i) qa[u][i] = 0.f;
#pragma unroll
      for (int kst = 0; kst < 8; ++kst) {
        uint32_t x0h0, x0h1, x0h2, x0h3, x0l0, x0l1, x0l2, x0l3;
        uint32_t x1h0, x1h1, x1h2, x1h3, x1l0, x1l1, x1l2, x1l3;
        ldsm4(x0h0, x0h1, x0h2, x0h3, aqBaseH + kst * 32);
        ldsm4(x0l0, x0l1, x0l2, x0l3, aqBaseL + kst * 32);
        ldsm4(x1h0, x1h1, x1h2, x1h3, aqBaseH + RT1 + kst * 32);
        ldsm4(x1l0, x1l1, x1l2, x1l3, aqBaseL + RT1 + kst * 32);
        const int fo = kst * 512 + ntbp * 32 + lane;
        uint4 f0 = wq[fo], f1 = wq[fo + 32];
        mma3(qa[0], x0h0, x0h1, x0h2, x0h3, x0l0, x0l1, x0l2, x0l3, f0);
        mma3(qa[1], x0h0, x0h1, x0h2, x0h3, x0l0, x0l1, x0l2, x0l3, f1);
        mma3(qa[2], x1h0, x1h1, x1h2, x1h3, x1l0, x1l1, x1l2, x1l3, f0);
        mma3(qa[3], x1h0, x1h1, x1h2, x1h3, x1l0, x1l1, x1l2, x1l3, f1);
      }
    }
    __syncthreads();                                           // (2) A reads done

    // q -> ahp fp16 (both passes)
#pragma unroll
    for (int p = 0; p < 2; ++p) {
      float (*qa)[4] = p ? q1 : q0;
#pragma unroll
      for (int rt = 0; rt < 2; ++rt)
#pragma unroll
        for (int tq = 0; tq < 2; ++tq) {
          const int u = rt * 2 + tq;
          const int rowA = wqm + rt * 16 + lm, rowB = rowA + 8;
          const int kp = (wqnB + p * 64 + tq * 8 + 2 * tig) >> 1;
          s.ahp[rowA][kp] = packh2(qa[u][0], qa[u][1]);
          s.ahp[rowB][kp] = packh2(qa[u][2], qa[u][3]);
        }
    }
    __syncthreads();                                           // (3)

    // ---- logits = q @ k^T (fp16; full m per warp) ----
    float aq[8][4];
#pragma unroll
    for (int t = 0; t < 8; ++t)
#pragma unroll
      for (int i = 0; i < 4; ++i) aq[t][i] = 0.f;
#pragma unroll
    for (int ks = 0; ks < 4; ++ks) {
      uint32_t ah0, ah1, ah2, ah3;
      ldsm4(ah0, ah1, ah2, ah3, aBaseH + (uint32_t)(hh * 32 + ks * 8) * 4);
#pragma unroll
      for (int tp = 0; tp < 4; ++tp) {
        uint32_t b0e, b1e, b0o, b1o;
        ldsm4(b0e, b1e, b0o, b1o,
              kB2 + (uint32_t)((tp * 16) * APAD + hh * 32 + ks * 8) * 4);
        mma_f16(aq[tp * 2],     ah0, ah1, ah2, ah3, b0e, b1e);
        mma_f16(aq[tp * 2 + 1], ah0, ah1, ah2, ah3, b0o, b1o);
      }
    }

    // ---- epilogue: edge bias (recomputed) + mask + warp-local softmax ----
    {
      const float w0 = s.Wel[l][0][hh], w1 = s.Wel[l][1][hh], w2 = s.Wel[l][2][hh],
                  w3 = s.Wel[l][3][hh], w4 = s.Wel[l][4][hh], w5 = s.Wel[l][5][hh],
                  w6 = s.Wel[l][6][hh];
      const bool okA = s.mrow[rA] > 0.f, okB = s.mrow[rB] > 0.f;
      const float a0 = s.coords[rA][0], a1 = s.coords[rA][1], a2 = s.coords[rA][2];
      const float b0 = s.coords[rB][0], b1 = s.coords[rB][1], b2 = s.coords[rB][2];
      float xA[16], xB[16];
#pragma unroll
      for (int t = 0; t < 8; ++t) {
#pragma unroll
        for (int j = 0; j < 2; ++j) {
          const int m = t * 8 + 2 * tig + j;
          const float m0 = s.coords[m][0], m1 = s.coords[m][1], m2 = s.coords[m][2];
          const bool okm = s.mrow[m] > 0.f;
          {
            float dx = a0 - m0, dy = a1 - m1, dz = a2 - m2;
            float d = sqrtf(dx * dx + dy * dy + dz * dz + 1e-12f);
            float ed = __expf(d);
            float g1 = __fdividef(ed, ed + 7.3890561f);
            float g2 = __fdividef(ed, ed + 54.598150f);
            float g3 = __fdividef(ed, ed + 403.42879f);
            float bias = dx * w0 + dy * w1 + dz * w2 + d * w3
                       + g1 * w4 + g2 * w5 + g3 * w6;
            xA[2 * t + j] = (okA && okm) ? aq[t][j] * INV_SQRT_DH + bias : NEGV;
          }
          {
            float dx = b0 - m0, dy = b1 - m1, dz = b2 - m2;
            float d = sqrtf(dx * dx + dy * dy + dz * dz + 1e-12f);
            float ed = __expf(d);
            float g1 = __fdividef(ed, ed + 7.3890561f);
            float g2 = __fdividef(ed, ed + 54.598150f);
            float g3 = __fdividef(ed, ed + 403.42879f);
            float bias = dx * w0 + dy * w1 + dz * w2 + d * w3
                       + g1 * w4 + g2 * w5 + g3 * w6;
            xB[2 * t + j] = (okB && okm) ? aq[t][2 + j] * INV_SQRT_DH + bias : NEGV;
          }
        }
      }
      float mxA = xA[0], mxB = xB[0];
#pragma unroll
      for (int i = 1; i < 16; ++i) { mxA = fmaxf(mxA, xA[i]); mxB = fmaxf(mxB, xB[i]); }
      mxA = fmaxf(mxA, __shfl_xor_sync(0xffffffffu, mxA, 1));
      mxA = fmaxf(mxA, __shfl_xor_sync(0xffffffffu, mxA, 2));
      mxB = fmaxf(mxB, __shfl_xor_sync(0xffffffffu, mxB, 1));
      mxB = fmaxf(mxB, __shfl_xor_sync(0xffffffffu, mxB, 2));
      float smA = 0.f, smB = 0.f;
#pragma unroll
      for (int i = 0; i < 16; ++i) {
        xA[i] = __expf(xA[i] - mxA); smA += xA[i];
        xB[i] = __expf(xB[i] - mxB); smB += xB[i];
      }
      smA += __shfl_xor_sync(0xffffffffu, smA, 1);
      smA += __shfl_xor_sync(0xffffffffu, smA, 2);
      smB += __shfl_xor_sync(0xffffffffu, smB, 1);
      smB += __shfl_xor_sync(0xffffffffu, smB, 2);
      const float invA = 1.f / smA, invB = 1.f / smB;
      __syncthreads();   // (4) all k-reads done before attn overwrites u1h
      const int baseA = (hh * 64 + rA) * TPAD;
      const int baseB = (hh * 64 + rB) * TPAD;
#pragma unroll
      for (int t = 0; t < 8; ++t) {
        int mp = t * 4 + tig;
        s.u1h[baseA + mp] = packh2(xA[2 * t] * invA, xA[2 * t + 1] * invA);
        s.u1h[baseB + mp] = packh2(xB[2 * t] * invB, xB[2 * t + 1] * invB);
      }
    }
    __syncwarp();   // attn rows are warp-private; order STS before ldsm

    // ---- msg = attn @ v (fp16; full dh per warp) -> split-bf16 into ahp/alp ----
#pragma unroll
    for (int t = 0; t < 8; ++t)
#pragma unroll
      for (int i = 0; i < 4; ++i) aq[t][i] = 0.f;
#pragma unroll
    for (int ks = 0; ks < 4; ++ks) {
      uint32_t ah0, ah1, ah2, ah3;
      ldsm4(ah0, ah1, ah2, ah3, atBaseH + (uint32_t)(ks * 8) * 4);
#pragma unroll
      for (int tp = 0; tp < 4; ++tp) {
        uint32_t b0e, b1e, b0o, b1o;
        ldsm4(b0e, b1e, b0o, b1o,
              vB2 + (uint32_t)((hh * 64 + tp * 16) * TPAD + ks * 8) * 4);
        mma_f16(aq[tp * 2],     ah0, ah1, ah2, ah3, b0e, b1e);
        mma_f16(aq[tp * 2 + 1], ah0, ah1, ah2, ah3, b0o, b1o);
      }
    }
#pragma unroll
    for (int t = 0; t < 8; ++t) {
      int kp = hh * 32 + t * 4 + tig;
      pack2(aq[t][0], aq[t][1], &s.ahp[rA][kp], &s.alp[rA][kp]);
      pack2(aq[t][2], aq[t][3], &s.ahp[rB][kp], &s.alp[rB][kp]);
    }
    __syncthreads();                                           // (6)

    // ---- h += msg @ Wo (2 passes) ----
#pragma unroll
    for (int p = 0; p < 2; ++p) {
      const int wqnp = wqnB + p * 64;
      const int ntbp = ((warp >> 1) + p * 4) << 1;
      float ak[4][4];
#pragma unroll
      for (int u = 0; u < 4; ++u)
#pragma unroll
        for (int i = 0; i < 4; ++i) ak[u][i] = 0.f;
#pragma unroll
      for (int kst = 0; kst < 8; ++kst) {
        uint32_t x0h0, x0h1, x0h2, x0h3, x0l0, x0l1, x0l2, x0l3;
        uint32_t x1h0, x1h1, x1h2, x1h3, x1l0, x1l1, x1l2, x1l3;
        ldsm4(x0h0, x0h1, x0h2, x0h3, aqBaseH + kst * 32);
        ldsm4(x0l0, x0l1, x0l2, x0l3, aqBaseL + kst * 32);
        ldsm4(x1h0, x1h1, x1h2, x1h3, aqBaseH + RT1 + kst * 32);
        ldsm4(x1l0, x1l1, x1l2, x1l3, aqBaseL + RT1 + kst * 32);
        const int fo = kst * 512 + ntbp * 32 + lane;
        uint4 f0 = wo[fo], f1 = wo[fo + 32];
        mma3(ak[0], x0h0, x0h1, x0h2, x0h3, x0l0, x0l1, x0l2, x0l3, f0);
        mma3(ak[1], x0h0, x0h1, x0h2, x0h3, x0l0, x0l1, x0l2, x0l3, f1);
        mma3(ak[2], x1h0, x1h1, x1h2, x1h3, x1l0, x1l1, x1l2, x1l3, f0);
        mma3(ak[3], x1h0, x1h1, x1h2, x1h3, x1l0, x1l1, x1l2, x1l3, f1);
      }
#pragma unroll
      for (int rt = 0; rt < 2; ++rt)
#pragma unroll
        for (int tq = 0; tq < 2; ++tq) {
          const int u = rt * 2 + tq;
          const int rA2 = wqm + rt * 16 + lm, rB2 = rA2 + 8;
          const int c2 = wqnp + tq * 8 + 2 * tig;
          float2 h0 = *(float2*)&s.h[rA2][c2];
          h0.x += ak[u][0]; h0.y += ak[u][1];
          *(float2*)&s.h[rA2][c2] = h0;
          float2 h1 = *(float2*)&s.h[rB2][c2];
          h1.x += ak[u][2]; h1.y += ak[u][3];
          *(float2*)&s.h[rB2][c2] = h1;
        }
    }
    __syncthreads();                                           // (7)

    // ---- LN(h) -> ahp/alp ----
    ln_split8(s.h, s.ahp, s.alp, tid);
    __syncthreads();                                           // (8)

    // ---- h = (h + tanh(LN(h) @ Wf + bf)) * mask (2 passes) ----
#pragma unroll
    for (int p = 0; p < 2; ++p) {
      const int wqnp = wqnB + p * 64;
      const int ntbp = ((warp >> 1) + p * 4) << 1;
      float ak[4][4];
#pragma unroll
      for (int u = 0; u < 4; ++u)
#pragma unroll
        for (int i = 0; i < 4; ++i) ak[u][i] = 0.f;
#pragma unroll
      for (int kst = 0; kst < 8; ++kst) {
        uint32_t x0h0, x0h1, x0h2, x0h3, x0l0, x0l1, x0l2, x0l3;
        uint32_t x1h0, x1h1, x1h2, x1h3, x1l0, x1l1, x1l2, x1l3;
        ldsm4(x0h0, x0h1, x0h2, x0h3, aqBaseH + kst * 32);
        ldsm4(x0l0, x0l1, x0l2, x0l3, aqBaseL + kst * 32);
        ldsm4(x1h0, x1h1, x1h2, x1h3, aqBaseH + RT1 + kst * 32);
        ldsm4(x1l0, x1l1, x1l2, x1l3, aqBaseL + RT1 + kst * 32);
        const int fo = kst * 512 + ntbp * 32 + lane;
        uint4 f0 = wf[fo], f1 = wf[fo + 32];
        mma3(ak[0], x0h0, x0h1, x0h2, x0h3, x0l0, x0l1, x0l2, x0l3, f0);
        mma3(ak[1], x0h0, x0h1, x0h2, x0h3, x0l0, x0l1, x0l2, x0l3, f1);
        mma3(ak[2], x1h0, x1h1, x1h2, x1h3, x1l0, x1l1, x1l2, x1l3, f0);
        mma3(ak[3], x1h0, x1h1, x1h2, x1h3, x1l0, x1l1, x1l2, x1l3, f1);
      }
#pragma unroll
      for (int rt = 0; rt < 2; ++rt)
#pragma unroll
        for (int tq = 0; tq < 2; ++tq) {
          const int u = rt * 2 + tq;
          const int rA2 = wqm + rt * 16 + lm, rB2 = rA2 + 8;
          const int c2 = wqnp + tq * 8 + 2 * tig;
          float mr0 = s.mrow[rA2], mr1 = s.mrow[rB2];
          float2 h0 = *(float2*)&s.h[rA2][c2];
          h0.x = (h0.x + tanhf(ak[u][0] + s.bf_all[l][c2]))     * mr0;
          h0.y = (h0.y + tanhf(ak[u][1] + s.bf_all[l][c2 + 1])) * mr0;
          *(float2*)&s.h[rA2][c2] = h0;
          float2 h1 = *(float2*)&s.h[rB2][c2];
          h1.x = (h1.x + tanhf(ak[u][2] + s.bf_all[l][c2]))     * mr1;
          h1.y = (h1.y + tanhf(ak[u][3] + s.bf_all[l][c2 + 1])) * mr1;
          *(float2*)&s.h[rB2][c2] = h1;
        }
    }
    __syncthreads();                                           // (9)
  }

  // ---- final layernorm -> global output ----
  {
    const int w = tid >> 5, ln = tid & 31;
    for (int n = w; n < N; n += 8) {
      float x0 = s.h[n][ln], x1 = s.h[n][ln + 32];
      float x2 = s.h[n][ln + 64], x3 = s.h[n][ln + 96];
      float sm = x0 + x1 + x2 + x3;
#pragma unroll
      for (int o = 16; o; o >>= 1) sm += __shfl_xor_sync(0xffffffffu, sm, o);
      float mean = sm * (1.f / 128.f);
      float d0 = x0 - mean, d1 = x1 - mean, d2 = x2 - mean, d3 = x3 - mean;
      float ss = d0 * d0 + d1 * d1 + d2 * d2 + d3 * d3;
#pragma unroll
      for (int o = 16; o; o >>= 1) ss += __shfl_xor_sync(0xffffffffu, ss, o);
      float inv = rsqrtf(ss * (1.f / 128.f) + 1e-5f);
      float* orow = g_out + (size_t)(b * N + n) * F;
      orow[ln]      = d0 * inv;
      orow[ln + 32] = d1 * inv;
      orow[ln + 64] = d2 * inv;
      orow[ln + 96] = d3 * inv;
    }
  }
}

// Split + fragment-order all 15 weight matrices.
__global__ void prep_weights(const float* __restrict__ Wq,
                             const float* __restrict__ Wk,
                             const float* __restrict__ Wv,
                             const float* __restrict__ Wo,
                             const float* __restrict__ Wf)
{
  int idx = blockIdx.x * blockDim.x + threadIdx.x;
  if (idx >= 15 * 8 * 16 * 32) return;
  int mat   = idx >> 12;
  int kst   = (idx >> 9) & 7;
  int ntile = (idx >> 5) & 15;
  int lane  = idx & 31;
  int l = mat / 5, which = mat % 5;
  const float* W =
      (which == 0 ? Wq : which == 1 ? Wk : which == 2 ? Wv : which == 3 ? Wo : Wf)
      + l * F * F;
  int n   = ntile * 8 + (lane >> 2);
  int kpA = kst * 8 + (lane & 3);
  int kpB = kpA + 4;

  float a0 = W[(2 * kpA)     * F + n];
  float a1 = W[(2 * kpA + 1) * F + n];
  float c0 = W[(2 * kpB)     * F + n];
  float c1 = W[(2 * kpB + 1) * F + n];

  __nv_bfloat162 ha = __floats2bfloat162_rn(a0, a1);
  __nv_bfloat162 la = __floats2bfloat162_rn(a0 - __bfloat162float(ha.x),
                                            a1 - __bfloat162float(ha.y));
  __nv_bfloat162 hc = __floats2bfloat162_rn(c0, c1);
  __nv_bfloat162 lc = __floats2bfloat162_rn(c0 - __bfloat162float(hc.x),
                                            c1 - __bfloat162float(hc.y));
  uint4 w;
  w.x = *reinterpret_cast<uint32_t*>(&ha);
  w.y = *reinterpret_cast<uint32_t*>(&hc);
  w.z = *reinterpret_cast<uint32_t*>(&la);
  w.w = *reinterpret_cast<uint32_t*>(&lc);
  g_wfrag[idx] = w;
}

}  // namespace

extern "C" void kernel_launch(void* const* d_in, const int* in_sizes, int n_in,
                              void* d_out, int out_size)
{
  (void)n_in; (void)out_size;
  const float* coords  = (const float*)d_in[0];
  const int*   species = (const int*)d_in[1];
  const int*   mask    = (const int*)d_in[2];
  const float* embed   = (const float*)d_in[3];
  const float* Wq      = (const float*)d_in[4];
  const float* Wk      = (const float*)d_in[5];
  const float* Wv      = (const float*)d_in[6];
  const float* Wo      = (const float*)d_in[7];
  const float* We      = (const float*)d_in[8];
  const float* Wf      = (const float*)d_in[9];
  const float* bf      = (const float*)d_in[10];

  const int B = in_sizes[0] / (N * 3);   // 2048

  prep_weights<<<(15 * 8 * 16 * 32 + 255) / 256, 256>>>(Wq, Wk, Wv, Wo, Wf);

  cudaFuncSetAttribute(gnn_kernel, cudaFuncAttributeMaxDynamicSharedMemorySize,
                       (int)sizeof(Smem));
  gnn_kernel<<<B, TPB, sizeof(Smem)>>>(coords, species, mask, embed,
                                       We, bf, (float*)d_out);
}